// round 1
// baseline (speedup 1.0000x reference)
#include <cuda_runtime.h>
#include <math.h>

#define BSZ 4
#define SEQ 2048
#define DMODEL 1024
#define NHEADS 16
#define DHEAD 64
#define MTOT (BSZ * SEQ)          // 8192
#define ATTN_SCALE 0.125f         // 1/sqrt(64)

// ---------------- scratch (device globals; no allocation) ----------------
__device__ float g_Q[(size_t)MTOT * DMODEL];
__device__ float g_K[(size_t)MTOT * DMODEL];
__device__ float g_V[(size_t)MTOT * DMODEL];
__device__ float g_O[(size_t)MTOT * DMODEL];

// ---------------- GEMM: C[M,1024] = A[M,1024] @ W[1024,1024]^T (+bias) ----
// 64x64 tile per block, BK=16, 256 threads, 4x4 per thread.
__global__ __launch_bounds__(256) void gemm64(const float* __restrict__ A,
                                              const float* __restrict__ W,
                                              const float* __restrict__ bias,
                                              float* __restrict__ C) {
    __shared__ float As[16][64];   // As[k][row]
    __shared__ float Bs[16][64];   // Bs[k][col]

    const int tid = threadIdx.x;
    const int tx = tid & 15;
    const int ty = tid >> 4;
    const int row0 = blockIdx.y * 64;   // M tile
    const int col0 = blockIdx.x * 64;   // N tile

    const int lr = tid >> 2;            // 0..63 (tile row for loads)
    const int lc = (tid & 3) * 4;       // 0,4,8,12

    const float* Ap = A + (size_t)(row0 + lr) * DMODEL + lc;
    const float* Wp = W + (size_t)(col0 + lr) * DMODEL + lc;

    float acc[4][4];
#pragma unroll
    for (int i = 0; i < 4; i++)
#pragma unroll
        for (int j = 0; j < 4; j++) acc[i][j] = 0.f;

    for (int bk = 0; bk < DMODEL; bk += 16) {
        float4 av = *(const float4*)(Ap + bk);
        float4 wv = *(const float4*)(Wp + bk);
        As[lc + 0][lr] = av.x; As[lc + 1][lr] = av.y;
        As[lc + 2][lr] = av.z; As[lc + 3][lr] = av.w;
        Bs[lc + 0][lr] = wv.x; Bs[lc + 1][lr] = wv.y;
        Bs[lc + 2][lr] = wv.z; Bs[lc + 3][lr] = wv.w;
        __syncthreads();

#pragma unroll
        for (int k = 0; k < 16; k++) {
            float4 a = *(const float4*)&As[k][ty * 4];
            float4 b = *(const float4*)&Bs[k][tx * 4];
            float ar[4] = {a.x, a.y, a.z, a.w};
            float br[4] = {b.x, b.y, b.z, b.w};
#pragma unroll
            for (int i = 0; i < 4; i++)
#pragma unroll
                for (int j = 0; j < 4; j++)
                    acc[i][j] = fmaf(ar[i], br[j], acc[i][j]);
        }
        __syncthreads();
    }

    float bi[4] = {0.f, 0.f, 0.f, 0.f};
    if (bias != nullptr) {
#pragma unroll
        for (int j = 0; j < 4; j++) bi[j] = bias[col0 + tx * 4 + j];
    }
#pragma unroll
    for (int i = 0; i < 4; i++) {
        float4 o;
        o.x = acc[i][0] + bi[0];
        o.y = acc[i][1] + bi[1];
        o.z = acc[i][2] + bi[2];
        o.w = acc[i][3] + bi[3];
        *(float4*)&C[(size_t)(row0 + ty * 4 + i) * DMODEL + col0 + tx * 4] = o;
    }
}

// ---------------- Flash attention: per (b,h), 64 query rows per block ------
// smem layout (floats):
//  Qs  [64][64]   scaled Q tile
//  Ks  [64][65]   K tile (padded)
//  Vs  [64][64]   V tile
//  Ss  [64][65]   scores / probs (padded)
//  mrow[64] lrow[64] arow[64]
#define QS_OFF 0
#define KS_OFF 4096
#define VS_OFF (4096 + 64 * 65)
#define SS_OFF (VS_OFF + 4096)
#define MR_OFF (SS_OFF + 64 * 65)
#define LR_OFF (MR_OFF + 64)
#define AR_OFF (LR_OFF + 64)
#define ATTN_SMEM_FLOATS (AR_OFF + 64)

__global__ __launch_bounds__(256) void attn_kernel(const float* __restrict__ Q,
                                                   const float* __restrict__ K,
                                                   const float* __restrict__ V,
                                                   float* __restrict__ O) {
    extern __shared__ float sm[];
    float* Qs = sm + QS_OFF;
    float* Ks = sm + KS_OFF;
    float* Vs = sm + VS_OFF;
    float* Ss = sm + SS_OFF;
    float* mrow = sm + MR_OFF;
    float* lrow = sm + LR_OFF;
    float* arow = sm + AR_OFF;

    const int tid = threadIdx.x;
    const int tx = tid & 15;
    const int ty = tid >> 4;
    const int bh = blockIdx.y;
    const int b = bh >> 4;
    const int h = bh & 15;
    const int q0 = blockIdx.x * 64;

    const size_t head_base = (size_t)b * SEQ * DMODEL + (size_t)h * DHEAD;
    const float* Qb = Q + head_base + (size_t)q0 * DMODEL;
    const float* Kb = K + head_base;
    const float* Vb = V + head_base;

    // load Q tile (scaled)
#pragma unroll
    for (int it = 0; it < 4; it++) {
        int slot = tid + it * 256;           // 1024 float4 slots
        int r = slot >> 4;
        int c4 = (slot & 15) * 4;
        float4 v = *(const float4*)(Qb + (size_t)r * DMODEL + c4);
        v.x *= ATTN_SCALE; v.y *= ATTN_SCALE; v.z *= ATTN_SCALE; v.w *= ATTN_SCALE;
        *(float4*)&Qs[r * 64 + c4] = v;
    }
    if (tid < 64) { mrow[tid] = -INFINITY; lrow[tid] = 0.f; }

    float acc[4][4];
#pragma unroll
    for (int i = 0; i < 4; i++)
#pragma unroll
        for (int j = 0; j < 4; j++) acc[i][j] = 0.f;

    const int ri0 = ty * 4;
    const int cj0 = tx * 4;

    for (int jb = 0; jb < SEQ / 64; jb++) {
        const float* Kt = Kb + (size_t)(jb * 64) * DMODEL;
        const float* Vt = Vb + (size_t)(jb * 64) * DMODEL;
        // load K (scalar, padded rows) and V (float4)
#pragma unroll
        for (int it = 0; it < 16; it++) {
            int e = tid + it * 256;          // 4096 elems
            int kr = e >> 6;
            int d = e & 63;
            Ks[kr * 65 + d] = Kt[(size_t)kr * DMODEL + d];
        }
#pragma unroll
        for (int it = 0; it < 4; it++) {
            int slot = tid + it * 256;
            int r = slot >> 4;
            int c4 = (slot & 15) * 4;
            *(float4*)&Vs[r * 64 + c4] = *(const float4*)(Vt + (size_t)r * DMODEL + c4);
        }
        __syncthreads();

        // S = Qs @ Ks^T  (4x4 per thread)
        float sacc[4][4];
#pragma unroll
        for (int i = 0; i < 4; i++)
#pragma unroll
            for (int j = 0; j < 4; j++) sacc[i][j] = 0.f;

#pragma unroll 4
        for (int d = 0; d < 64; d++) {
            float qv[4], kv[4];
#pragma unroll
            for (int i = 0; i < 4; i++) qv[i] = Qs[(ri0 + i) * 64 + d];
#pragma unroll
            for (int j = 0; j < 4; j++) kv[j] = Ks[(cj0 + j) * 65 + d];
#pragma unroll
            for (int i = 0; i < 4; i++)
#pragma unroll
                for (int j = 0; j < 4; j++)
                    sacc[i][j] = fmaf(qv[i], kv[j], sacc[i][j]);
        }
#pragma unroll
        for (int i = 0; i < 4; i++)
#pragma unroll
            for (int j = 0; j < 4; j++)
                Ss[(ri0 + i) * 65 + cj0 + j] = sacc[i][j];
        __syncthreads();

        // row max + alpha (64 row-threads)
        if (tid < 64) {
            float mold = mrow[tid];
            float mx = mold;
            const float* srow = &Ss[tid * 65];
#pragma unroll 8
            for (int c = 0; c < 64; c++) mx = fmaxf(mx, srow[c]);
            mrow[tid] = mx;
            arow[tid] = __expf(mold - mx);
        }
        __syncthreads();

        // exponentiate own tile, write P back to Ss
#pragma unroll
        for (int i = 0; i < 4; i++) {
            float mi = mrow[ri0 + i];
#pragma unroll
            for (int j = 0; j < 4; j++)
                Ss[(ri0 + i) * 65 + cj0 + j] = __expf(sacc[i][j] - mi);
        }
        __syncthreads();

        // l update (row-threads) in parallel with O accumulation (all threads)
        if (tid < 64) {
            const float* prow = &Ss[tid * 65];
            float s = 0.f;
#pragma unroll 8
            for (int c = 0; c < 64; c++) s += prow[c];
            lrow[tid] = lrow[tid] * arow[tid] + s;
        }

        // O = O*alpha + P @ V
        float al[4];
#pragma unroll
        for (int i = 0; i < 4; i++) al[i] = arow[ri0 + i];
#pragma unroll
        for (int i = 0; i < 4; i++)
#pragma unroll
            for (int j = 0; j < 4; j++) acc[i][j] *= al[i];

#pragma unroll 4
        for (int kk = 0; kk < 64; kk++) {
            float pv[4], vv[4];
#pragma unroll
            for (int i = 0; i < 4; i++) pv[i] = Ss[(ri0 + i) * 65 + kk];
#pragma unroll
            for (int j = 0; j < 4; j++) vv[j] = Vs[kk * 64 + cj0 + j];
#pragma unroll
            for (int i = 0; i < 4; i++)
#pragma unroll
                for (int j = 0; j < 4; j++)
                    acc[i][j] = fmaf(pv[i], vv[j], acc[i][j]);
        }
        __syncthreads();
    }

    // normalize + write out (same [M, DMODEL] layout as Q)
    float* Ob = O + head_base + (size_t)q0 * DMODEL;
#pragma unroll
    for (int i = 0; i < 4; i++) {
        float inv = 1.f / lrow[ri0 + i];
        float4 o;
        o.x = acc[i][0] * inv;
        o.y = acc[i][1] * inv;
        o.z = acc[i][2] * inv;
        o.w = acc[i][3] * inv;
        *(float4*)&Ob[(size_t)(ri0 + i) * DMODEL + cj0] = o;
    }
}

extern "C" void kernel_launch(void* const* d_in, const int* in_sizes, int n_in,
                              void* d_out, int out_size) {
    const float* x  = (const float*)d_in[0];
    const float* Wq = (const float*)d_in[1];
    const float* Wk = (const float*)d_in[2];
    const float* Wv = (const float*)d_in[3];
    const float* Wo = (const float*)d_in[4];
    const float* bo = (const float*)d_in[5];
    float* out = (float*)d_out;

    void *pQ, *pK, *pV, *pO;
    cudaGetSymbolAddress(&pQ, g_Q);
    cudaGetSymbolAddress(&pK, g_K);
    cudaGetSymbolAddress(&pV, g_V);
    cudaGetSymbolAddress(&pO, g_O);

    const int attn_smem = ATTN_SMEM_FLOATS * (int)sizeof(float);  // 66816 B
    cudaFuncSetAttribute(attn_kernel, cudaFuncAttributeMaxDynamicSharedMemorySize,
                         attn_smem);

    dim3 ggrid(DMODEL / 64, MTOT / 64);   // (16, 128)
    gemm64<<<ggrid, 256>>>(x, Wq, nullptr, (float*)pQ);
    gemm64<<<ggrid, 256>>>(x, Wk, nullptr, (float*)pK);
    gemm64<<<ggrid, 256>>>(x, Wv, nullptr, (float*)pV);

    dim3 agrid(SEQ / 64, BSZ * NHEADS);   // (32, 64)
    attn_kernel<<<agrid, 256, attn_smem>>>((const float*)pQ, (const float*)pK,
                                           (const float*)pV, (float*)pO);

    gemm64<<<ggrid, 256>>>((const float*)pO, Wo, bo, out);
}

// round 2
// speedup vs baseline: 2.6418x; 2.6418x over previous
#include <cuda_runtime.h>
#include <math.h>

#define BSZ 4
#define SEQ 2048
#define DMODEL 1024
#define NHEADS 16
#define DHEAD 64
#define MTOT (BSZ * SEQ)          // 8192
#define ATTN_SCALE 0.125f

// ---------------- scratch ----------------
__device__ float g_Q[(size_t)MTOT * DMODEL];
__device__ float g_K[(size_t)MTOT * DMODEL];
__device__ float g_V[(size_t)MTOT * DMODEL];
__device__ float g_O[(size_t)MTOT * DMODEL];

// ---------------- helpers ----------------
__device__ __forceinline__ unsigned f2t(float x) {
    unsigned u;
    asm("cvt.rna.tf32.f32 %0, %1;" : "=r"(u) : "f"(x));
    return u;
}

__device__ __forceinline__ void mma8(float* c, const unsigned* a, const unsigned* b) {
    asm volatile(
        "mma.sync.aligned.m16n8k8.row.col.f32.tf32.tf32.f32 "
        "{%0,%1,%2,%3}, {%4,%5,%6,%7}, {%8,%9}, {%0,%1,%2,%3};"
        : "+f"(c[0]), "+f"(c[1]), "+f"(c[2]), "+f"(c[3])
        : "r"(a[0]), "r"(a[1]), "r"(a[2]), "r"(a[3]), "r"(b[0]), "r"(b[1]));
}

// ---------------- tf32 GEMM: C[M,1024] = A @ W^T (+bias) ----------------
// 128x128 tile, BK=16, 256 threads (8 warps: 2m x 4n), warp tile 64x32.
__device__ __forceinline__ void gemm_body(const float* __restrict__ A,
                                          const float* __restrict__ W,
                                          const float* __restrict__ bias,
                                          float* __restrict__ C) {
    __shared__ unsigned As[128 * 20];
    __shared__ unsigned Bs[128 * 20];

    const int tid = threadIdx.x;
    const int warp = tid >> 5, lane = tid & 31;
    const int qd = lane >> 2, r = lane & 3;
    const int wm = (warp & 1) * 64;
    const int wn = (warp >> 1) * 32;
    const int row0 = blockIdx.y * 128;
    const int col0 = blockIdx.x * 128;

    const int lr = tid >> 1;
    const int lc = (tid & 1) * 8;
    const float* Ap = A + (size_t)(row0 + lr) * DMODEL + lc;
    const float* Wp = W + (size_t)(col0 + lr) * DMODEL + lc;

    float acc[4][4][4];
#pragma unroll
    for (int mt = 0; mt < 4; mt++)
#pragma unroll
        for (int nt = 0; nt < 4; nt++)
#pragma unroll
            for (int i = 0; i < 4; i++) acc[mt][nt][i] = 0.f;

    for (int bk = 0; bk < DMODEL; bk += 16) {
        float4 a0 = *(const float4*)(Ap + bk);
        float4 a1 = *(const float4*)(Ap + bk + 4);
        float4 w0 = *(const float4*)(Wp + bk);
        float4 w1 = *(const float4*)(Wp + bk + 4);
        *(uint4*)&As[lr * 20 + lc]     = make_uint4(f2t(a0.x), f2t(a0.y), f2t(a0.z), f2t(a0.w));
        *(uint4*)&As[lr * 20 + lc + 4] = make_uint4(f2t(a1.x), f2t(a1.y), f2t(a1.z), f2t(a1.w));
        *(uint4*)&Bs[lr * 20 + lc]     = make_uint4(f2t(w0.x), f2t(w0.y), f2t(w0.z), f2t(w0.w));
        *(uint4*)&Bs[lr * 20 + lc + 4] = make_uint4(f2t(w1.x), f2t(w1.y), f2t(w1.z), f2t(w1.w));
        __syncthreads();

#pragma unroll
        for (int ks = 0; ks < 2; ks++) {
            unsigned af[4][4], bf[4][2];
#pragma unroll
            for (int mt = 0; mt < 4; mt++) {
                int mr = wm + mt * 16;
                af[mt][0] = As[(mr + qd) * 20 + ks * 8 + r];
                af[mt][1] = As[(mr + qd + 8) * 20 + ks * 8 + r];
                af[mt][2] = As[(mr + qd) * 20 + ks * 8 + r + 4];
                af[mt][3] = As[(mr + qd + 8) * 20 + ks * 8 + r + 4];
            }
#pragma unroll
            for (int nt = 0; nt < 4; nt++) {
                int nc = wn + nt * 8;
                bf[nt][0] = Bs[(nc + qd) * 20 + ks * 8 + r];
                bf[nt][1] = Bs[(nc + qd) * 20 + ks * 8 + r + 4];
            }
#pragma unroll
            for (int mt = 0; mt < 4; mt++)
#pragma unroll
                for (int nt = 0; nt < 4; nt++)
                    mma8(acc[mt][nt], af[mt], bf[nt]);
        }
        __syncthreads();
    }

#pragma unroll
    for (int mt = 0; mt < 4; mt++) {
        int rlo = row0 + wm + mt * 16 + qd;
#pragma unroll
        for (int nt = 0; nt < 4; nt++) {
            int col = col0 + wn + nt * 8 + 2 * r;
            float b0 = bias ? bias[col] : 0.f;
            float b1 = bias ? bias[col + 1] : 0.f;
            float2 lo = make_float2(acc[mt][nt][0] + b0, acc[mt][nt][1] + b1);
            float2 hi = make_float2(acc[mt][nt][2] + b0, acc[mt][nt][3] + b1);
            *(float2*)&C[(size_t)rlo * DMODEL + col] = lo;
            *(float2*)&C[(size_t)(rlo + 8) * DMODEL + col] = hi;
        }
    }
}

__global__ __launch_bounds__(256, 2) void gemm_qkv(const float* __restrict__ x,
                                                   const float* __restrict__ Wq,
                                                   const float* __restrict__ Wk,
                                                   const float* __restrict__ Wv,
                                                   float* __restrict__ Qo,
                                                   float* __restrict__ Ko,
                                                   float* __restrict__ Vo) {
    const float* W = (blockIdx.z == 0) ? Wq : (blockIdx.z == 1) ? Wk : Wv;
    float* C = (blockIdx.z == 0) ? Qo : (blockIdx.z == 1) ? Ko : Vo;
    gemm_body(x, W, nullptr, C);
}

__global__ __launch_bounds__(256, 2) void gemm_out(const float* __restrict__ A,
                                                   const float* __restrict__ W,
                                                   const float* __restrict__ bias,
                                                   float* __restrict__ C) {
    gemm_body(A, W, bias, C);
}

// ---------------- tf32 flash attention ----------------
// Block: one (b,h), 64 query rows. 256 threads, 8 warps.
// S (64x64) warp tiling: 4(m=q) x 2(n=key) warps, each m16 x n32.
// PV computed as O^T = V^T @ P^T: 4(m=d) x 2(n=q) warps, each m16 x n32.
// smem strides: Ks/Ss = 68 (conflict-free B-frag loads), Vs = 72 (conflict-free
// A-frag loads of V^T).
#define KS_W 68
#define VS_W 72
#define SS_W 68
#define ATTN_SMEM_WORDS (64 * KS_W + 64 * VS_W + 64 * SS_W + 64 * 3 + 256)

__global__ __launch_bounds__(256, 2) void attn_tf32(const float* __restrict__ Q,
                                                    const float* __restrict__ K,
                                                    const float* __restrict__ V,
                                                    float* __restrict__ O) {
    extern __shared__ unsigned sm[];
    unsigned* Ks = sm;                       // 64*68
    unsigned* Vs = Ks + 64 * KS_W;           // 64*72
    unsigned* Ss = Vs + 64 * VS_W;           // 64*68 (tf32 bits)
    float* mrow = (float*)(Ss + 64 * SS_W);  // 64
    float* lrow = mrow + 64;                 // 64
    float* arow = lrow + 64;                 // 64
    float* wmax = arow + 64;                 // [2][64]
    float* wsum = wmax + 128;                // [2][64]

    const int tid = threadIdx.x;
    const int warp = tid >> 5, lane = tid & 31;
    const int qd = lane >> 2, r = lane & 3;
    const int m0 = (warp & 3) * 16;   // S: q-tile base; PV: d-tile base
    const int wn = warp >> 2;         // 0/1
    const int n0 = wn * 32;           // S: key base; PV: q-col base

    const int bh = blockIdx.y;
    const int b = bh >> 4, h = bh & 15;
    const int q0 = blockIdx.x * 64;
    const size_t hb = (size_t)b * SEQ * DMODEL + (size_t)h * DHEAD;

    const int trow = tid >> 2;            // 0..63
    const int tc = (tid & 3) * 16;        // 0,16,32,48

    // stage scaled Q (tf32) into Ss
    {
        const float* Qp = Q + hb + (size_t)(q0 + trow) * DMODEL + tc;
#pragma unroll
        for (int i = 0; i < 4; i++) {
            float4 v = *(const float4*)(Qp + 4 * i);
            *(uint4*)&Ss[trow * SS_W + tc + 4 * i] =
                make_uint4(f2t(v.x * ATTN_SCALE), f2t(v.y * ATTN_SCALE),
                           f2t(v.z * ATTN_SCALE), f2t(v.w * ATTN_SCALE));
        }
    }
    if (tid < 64) { mrow[tid] = -INFINITY; lrow[tid] = 0.f; }
    __syncthreads();

    // Q fragments in registers for the whole kernel (8 k-steps x 4 regs)
    unsigned qf[8][4];
#pragma unroll
    for (int ks = 0; ks < 8; ks++) {
        qf[ks][0] = Ss[(m0 + qd) * SS_W + ks * 8 + r];
        qf[ks][1] = Ss[(m0 + qd + 8) * SS_W + ks * 8 + r];
        qf[ks][2] = Ss[(m0 + qd) * SS_W + ks * 8 + r + 4];
        qf[ks][3] = Ss[(m0 + qd + 8) * SS_W + ks * 8 + r + 4];
    }

    float oacc[4][4];
#pragma unroll
    for (int nt = 0; nt < 4; nt++)
#pragma unroll
        for (int i = 0; i < 4; i++) oacc[nt][i] = 0.f;

    for (int jb = 0; jb < SEQ / 64; jb++) {
        __syncthreads();  // (a) prior-iter Ss/Vs reads complete; Q frags extracted
        {
            const float* Kp = K + hb + (size_t)(jb * 64 + trow) * DMODEL + tc;
            const float* Vp = V + hb + (size_t)(jb * 64 + trow) * DMODEL + tc;
#pragma unroll
            for (int i = 0; i < 4; i++) {
                float4 kv = *(const float4*)(Kp + 4 * i);
                *(uint4*)&Ks[trow * KS_W + tc + 4 * i] =
                    make_uint4(f2t(kv.x), f2t(kv.y), f2t(kv.z), f2t(kv.w));
                float4 vv = *(const float4*)(Vp + 4 * i);
                *(uint4*)&Vs[trow * VS_W + tc + 4 * i] =
                    make_uint4(f2t(vv.x), f2t(vv.y), f2t(vv.z), f2t(vv.w));
            }
        }
        __syncthreads();  // (b) tiles ready

        // S = Q K^T (warp m16 x n32)
        float sa[4][4];
#pragma unroll
        for (int nt = 0; nt < 4; nt++)
#pragma unroll
            for (int i = 0; i < 4; i++) sa[nt][i] = 0.f;

#pragma unroll
        for (int ks = 0; ks < 8; ks++) {
#pragma unroll
            for (int nt = 0; nt < 4; nt++) {
                unsigned bf[2];
                bf[0] = Ks[(n0 + nt * 8 + qd) * KS_W + ks * 8 + r];
                bf[1] = Ks[(n0 + nt * 8 + qd) * KS_W + ks * 8 + r + 4];
                mma8(sa[nt], qf[ks], bf);
            }
        }

        // register-level row max (per thread: rows m0+qd, m0+qd+8)
        float mx0 = sa[0][0], mx1 = sa[0][2];
#pragma unroll
        for (int nt = 0; nt < 4; nt++) {
            mx0 = fmaxf(mx0, fmaxf(sa[nt][0], sa[nt][1]));
            mx1 = fmaxf(mx1, fmaxf(sa[nt][2], sa[nt][3]));
        }
        mx0 = fmaxf(mx0, __shfl_xor_sync(0xffffffffu, mx0, 1));
        mx0 = fmaxf(mx0, __shfl_xor_sync(0xffffffffu, mx0, 2));
        mx1 = fmaxf(mx1, __shfl_xor_sync(0xffffffffu, mx1, 1));
        mx1 = fmaxf(mx1, __shfl_xor_sync(0xffffffffu, mx1, 2));
        if (r == 0) {
            wmax[wn * 64 + m0 + qd] = mx0;
            wmax[wn * 64 + m0 + qd + 8] = mx1;
        }
        __syncthreads();  // (c) wmax ready

        if (tid < 64) {
            float mo = mrow[tid];
            float mn = fmaxf(mo, fmaxf(wmax[tid], wmax[64 + tid]));
            arow[tid] = __expf(mo - mn);
            mrow[tid] = mn;
        }
        __syncthreads();  // (d) mrow/arow ready

        {
            float mlo = mrow[m0 + qd], mhi = mrow[m0 + qd + 8];
            float s0 = 0.f, s1 = 0.f;
#pragma unroll
            for (int nt = 0; nt < 4; nt++) {
                unsigned u0 = f2t(__expf(sa[nt][0] - mlo));
                unsigned u1 = f2t(__expf(sa[nt][1] - mlo));
                unsigned u2 = f2t(__expf(sa[nt][2] - mhi));
                unsigned u3 = f2t(__expf(sa[nt][3] - mhi));
                s0 += __uint_as_float(u0) + __uint_as_float(u1);
                s1 += __uint_as_float(u2) + __uint_as_float(u3);
                *(uint2*)&Ss[(m0 + qd) * SS_W + n0 + nt * 8 + 2 * r] = make_uint2(u0, u1);
                *(uint2*)&Ss[(m0 + qd + 8) * SS_W + n0 + nt * 8 + 2 * r] = make_uint2(u2, u3);
            }
            s0 += __shfl_xor_sync(0xffffffffu, s0, 1);
            s0 += __shfl_xor_sync(0xffffffffu, s0, 2);
            s1 += __shfl_xor_sync(0xffffffffu, s1, 1);
            s1 += __shfl_xor_sync(0xffffffffu, s1, 2);
            if (r == 0) {
                wsum[wn * 64 + m0 + qd] = s0;
                wsum[wn * 64 + m0 + qd + 8] = s1;
            }
        }

        // rescale O^T accumulators by alpha per q-column
#pragma unroll
        for (int nt = 0; nt < 4; nt++) {
            float a0 = arow[n0 + nt * 8 + 2 * r];
            float a1 = arow[n0 + nt * 8 + 2 * r + 1];
            oacc[nt][0] *= a0; oacc[nt][1] *= a1;
            oacc[nt][2] *= a0; oacc[nt][3] *= a1;
        }
        __syncthreads();  // (e) P + wsum ready

        if (tid < 64) lrow[tid] = lrow[tid] * arow[tid] + wsum[tid] + wsum[64 + tid];

        // O^T += V^T @ P^T (warp m16(d) x n32(q))
#pragma unroll
        for (int ks = 0; ks < 8; ks++) {
            unsigned av[4];
            av[0] = Vs[(ks * 8 + r) * VS_W + m0 + qd];
            av[1] = Vs[(ks * 8 + r) * VS_W + m0 + qd + 8];
            av[2] = Vs[(ks * 8 + r + 4) * VS_W + m0 + qd];
            av[3] = Vs[(ks * 8 + r + 4) * VS_W + m0 + qd + 8];
#pragma unroll
            for (int nt = 0; nt < 4; nt++) {
                unsigned bp[2];
                bp[0] = Ss[(n0 + nt * 8 + qd) * SS_W + ks * 8 + r];
                bp[1] = Ss[(n0 + nt * 8 + qd) * SS_W + ks * 8 + r + 4];
                mma8(oacc[nt], av, bp);
            }
        }
    }
    __syncthreads();  // final lrow ready

    // epilogue: normalize, write O (rows=q, contiguous d)
    float* Op = O + hb + (size_t)q0 * DMODEL;
#pragma unroll
    for (int nt = 0; nt < 4; nt++) {
        int c0 = n0 + nt * 8 + 2 * r;
        float i0 = 1.f / lrow[c0];
        float i1 = 1.f / lrow[c0 + 1];
        int d0 = m0 + qd;
        Op[(size_t)c0 * DMODEL + d0]           = oacc[nt][0] * i0;
        Op[(size_t)(c0 + 1) * DMODEL + d0]     = oacc[nt][1] * i1;
        Op[(size_t)c0 * DMODEL + d0 + 8]       = oacc[nt][2] * i0;
        Op[(size_t)(c0 + 1) * DMODEL + d0 + 8] = oacc[nt][3] * i1;
    }
}

extern "C" void kernel_launch(void* const* d_in, const int* in_sizes, int n_in,
                              void* d_out, int out_size) {
    const float* x  = (const float*)d_in[0];
    const float* Wq = (const float*)d_in[1];
    const float* Wk = (const float*)d_in[2];
    const float* Wv = (const float*)d_in[3];
    const float* Wo = (const float*)d_in[4];
    const float* bo = (const float*)d_in[5];
    float* out = (float*)d_out;

    void *pQ, *pK, *pV, *pO;
    cudaGetSymbolAddress(&pQ, g_Q);
    cudaGetSymbolAddress(&pK, g_K);
    cudaGetSymbolAddress(&pV, g_V);
    cudaGetSymbolAddress(&pO, g_O);

    const int attn_smem = ATTN_SMEM_WORDS * (int)sizeof(unsigned);  // 55040 B
    cudaFuncSetAttribute(attn_tf32, cudaFuncAttributeMaxDynamicSharedMemorySize,
                         attn_smem);

    dim3 ggrid(DMODEL / 128, MTOT / 128, 3);  // (8, 64, 3)
    gemm_qkv<<<ggrid, 256>>>(x, Wq, Wk, Wv, (float*)pQ, (float*)pK, (float*)pV);

    dim3 agrid(SEQ / 64, BSZ * NHEADS);       // (32, 64)
    attn_tf32<<<agrid, 256, attn_smem>>>((const float*)pQ, (const float*)pK,
                                         (const float*)pV, (float*)pO);

    dim3 ogrid(DMODEL / 128, MTOT / 128, 1);
    gemm_out<<<ogrid, 256>>>((const float*)pO, Wo, bo, out);
}

// round 9
// speedup vs baseline: 3.4941x; 1.3226x over previous
#include <cuda_runtime.h>
#include <math.h>

#define BSZ 4
#define SEQ 2048
#define DMODEL 1024
#define NHEADS 16
#define DHEAD 64
#define MTOT (BSZ * SEQ)          // 8192
#define ATTN_SCALE 0.125f

// ---------------- scratch ----------------
__device__ float g_Q[(size_t)MTOT * DMODEL];
__device__ float g_K[(size_t)MTOT * DMODEL];
__device__ float g_V[(size_t)MTOT * DMODEL];
__device__ float g_O[(size_t)MTOT * DMODEL];

// ---------------- helpers ----------------
__device__ __forceinline__ unsigned f2t(float x) {
    unsigned u;
    asm("cvt.rna.tf32.f32 %0, %1;" : "=r"(u) : "f"(x));
    return u;
}

__device__ __forceinline__ void mma8(float* c, const unsigned* a, const unsigned* b) {
    asm volatile(
        "mma.sync.aligned.m16n8k8.row.col.f32.tf32.tf32.f32 "
        "{%0,%1,%2,%3}, {%4,%5,%6,%7}, {%8,%9}, {%0,%1,%2,%3};"
        : "+f"(c[0]), "+f"(c[1]), "+f"(c[2]), "+f"(c[3])
        : "r"(a[0]), "r"(a[1]), "r"(a[2]), "r"(a[3]), "r"(b[0]), "r"(b[1]));
}

__device__ __forceinline__ void cp16(float* dst, const float* src) {
    unsigned d = (unsigned)__cvta_generic_to_shared(dst);
    asm volatile("cp.async.cg.shared.global [%0], [%1], 16;" :: "r"(d), "l"(src));
}
__device__ __forceinline__ void cp_commit() {
    asm volatile("cp.async.commit_group;");
}
__device__ __forceinline__ void cp_wait1() {
    asm volatile("cp.async.wait_group 1;");
}
__device__ __forceinline__ void cp_wait0() {
    asm volatile("cp.async.wait_group 0;");
}

// ---------------- tf32 GEMM: C[M,1024] = A @ W^T (+bias) ----------------
// 128x128 tile, BK=16, 256 threads (8 warps: 2m x 4n), warp tile 64x32.
// 2-stage cp.async pipeline; tf32 conversion at fragment load.
__device__ __forceinline__ void gemm_body(const float* __restrict__ A,
                                          const float* __restrict__ W,
                                          const float* __restrict__ bias,
                                          float* __restrict__ C) {
    __shared__ float As[2][128 * 20];
    __shared__ float Bs[2][128 * 20];

    const int tid = threadIdx.x;
    const int warp = tid >> 5, lane = tid & 31;
    const int qd = lane >> 2, r = lane & 3;
    const int wm = (warp & 1) * 64;
    const int wn = (warp >> 1) * 32;
    const int row0 = blockIdx.y * 128;
    const int col0 = blockIdx.x * 128;

    // cp.async chunk coords: 512 16B-chunks per 128x16 tile; 2 chunks/thread/tensor
    const int cr = tid >> 2;            // 0..63
    const int cc = (tid & 3) * 4;       // 0,4,8,12
    const float* Ap0 = A + (size_t)(row0 + cr) * DMODEL + cc;
    const float* Ap1 = A + (size_t)(row0 + cr + 64) * DMODEL + cc;
    const float* Wp0 = W + (size_t)(col0 + cr) * DMODEL + cc;
    const float* Wp1 = W + (size_t)(col0 + cr + 64) * DMODEL + cc;
    const int so0 = cr * 20 + cc;
    const int so1 = (cr + 64) * 20 + cc;

    float acc[4][4][4];
#pragma unroll
    for (int mt = 0; mt < 4; mt++)
#pragma unroll
        for (int nt = 0; nt < 4; nt++)
#pragma unroll
            for (int i = 0; i < 4; i++) acc[mt][nt][i] = 0.f;

    // prologue: stage bk=0 into buf 0
    cp16(&As[0][so0], Ap0);
    cp16(&As[0][so1], Ap1);
    cp16(&Bs[0][so0], Wp0);
    cp16(&Bs[0][so1], Wp1);
    cp_commit();

    int buf = 0;
#pragma unroll 1
    for (int bk = 0; bk < DMODEL; bk += 16, buf ^= 1) {
        if (bk + 16 < DMODEL) {
            cp16(&As[buf ^ 1][so0], Ap0 + bk + 16);
            cp16(&As[buf ^ 1][so1], Ap1 + bk + 16);
            cp16(&Bs[buf ^ 1][so0], Wp0 + bk + 16);
            cp16(&Bs[buf ^ 1][so1], Wp1 + bk + 16);
            cp_commit();
            cp_wait1();
        } else {
            cp_wait0();
        }
        __syncthreads();

        const float* Ab = As[buf];
        const float* Bb = Bs[buf];
#pragma unroll
        for (int ks = 0; ks < 2; ks++) {
            unsigned af[4][4], bf[4][2];
#pragma unroll
            for (int mt = 0; mt < 4; mt++) {
                int mr = wm + mt * 16;
                af[mt][0] = f2t(Ab[(mr + qd) * 20 + ks * 8 + r]);
                af[mt][1] = f2t(Ab[(mr + qd + 8) * 20 + ks * 8 + r]);
                af[mt][2] = f2t(Ab[(mr + qd) * 20 + ks * 8 + r + 4]);
                af[mt][3] = f2t(Ab[(mr + qd + 8) * 20 + ks * 8 + r + 4]);
            }
#pragma unroll
            for (int nt = 0; nt < 4; nt++) {
                int nc = wn + nt * 8;
                bf[nt][0] = f2t(Bb[(nc + qd) * 20 + ks * 8 + r]);
                bf[nt][1] = f2t(Bb[(nc + qd) * 20 + ks * 8 + r + 4]);
            }
#pragma unroll
            for (int mt = 0; mt < 4; mt++)
#pragma unroll
                for (int nt = 0; nt < 4; nt++)
                    mma8(acc[mt][nt], af[mt], bf[nt]);
        }
        __syncthreads();
    }

#pragma unroll
    for (int mt = 0; mt < 4; mt++) {
        int rlo = row0 + wm + mt * 16 + qd;
#pragma unroll
        for (int nt = 0; nt < 4; nt++) {
            int col = col0 + wn + nt * 8 + 2 * r;
            float b0 = bias ? bias[col] : 0.f;
            float b1 = bias ? bias[col + 1] : 0.f;
            float2 lo = make_float2(acc[mt][nt][0] + b0, acc[mt][nt][1] + b1);
            float2 hi = make_float2(acc[mt][nt][2] + b0, acc[mt][nt][3] + b1);
            *(float2*)&C[(size_t)rlo * DMODEL + col] = lo;
            *(float2*)&C[(size_t)(rlo + 8) * DMODEL + col] = hi;
        }
    }
}

__global__ __launch_bounds__(256, 2) void gemm_qkv(const float* __restrict__ x,
                                                   const float* __restrict__ Wq,
                                                   const float* __restrict__ Wk,
                                                   const float* __restrict__ Wv,
                                                   float* __restrict__ Qo,
                                                   float* __restrict__ Ko,
                                                   float* __restrict__ Vo) {
    const float* W = (blockIdx.z == 0) ? Wq : (blockIdx.z == 1) ? Wk : Wv;
    float* C = (blockIdx.z == 0) ? Qo : (blockIdx.z == 1) ? Ko : Vo;
    gemm_body(x, W, nullptr, C);
}

__global__ __launch_bounds__(256, 2) void gemm_out(const float* __restrict__ A,
                                                   const float* __restrict__ W,
                                                   const float* __restrict__ bias,
                                                   float* __restrict__ C) {
    gemm_body(A, W, bias, C);
}

// ---------------- tf32 flash attention ----------------
// Block: one (b,h), 64 query rows, 256 threads (8 warps).
// S: 4(m=q) x 2(n=key) warps, m16 x n32 each. PV as O^T = V^T @ P^T.
// K/V staged raw fp32 via 2-stage cp.async; tf32 cvt at fragment load.
// Strides: Ks/Ss = 68, Vs = 72 (all fragment accesses conflict-free).
#define KS_W 68
#define VS_W 72
#define SS_W 68
#define KS_SZ (64 * KS_W)  // 4352
#define VS_SZ (64 * VS_W)  // 4608
// floats: 2*KS_SZ + 2*VS_SZ + SS + mrow2(128) + lrow(64) + wmax(128) + wsum(128)
#define OFF_V (2 * KS_SZ)
#define OFF_S (2 * KS_SZ + 2 * VS_SZ)
#define OFF_M (OFF_S + 64 * SS_W)
#define OFF_L (OFF_M + 128)
#define OFF_WM (OFF_L + 64)
#define OFF_WS (OFF_WM + 128)
#define ATTN_SMEM_WORDS (OFF_WS + 128)   // 22720 -> 90880 B

__global__ __launch_bounds__(256, 2) void attn_tf32(const float* __restrict__ Q,
                                                    const float* __restrict__ K,
                                                    const float* __restrict__ V,
                                                    float* __restrict__ O) {
    extern __shared__ float smf[];
    float* KsBuf = smf;                  // [2][KS_SZ]
    float* VsBuf = smf + OFF_V;          // [2][VS_SZ]
    unsigned* Ss = (unsigned*)(smf + OFF_S);
    float* mrow2 = smf + OFF_M;          // ping-pong [2][64]
    float* lrow = smf + OFF_L;
    float* wmax = smf + OFF_WM;          // [2][64]
    float* wsum = smf + OFF_WS;          // [2][64]

    const int tid = threadIdx.x;
    const int warp = tid >> 5, lane = tid & 31;
    const int qd = lane >> 2, r = lane & 3;
    const int m0 = (warp & 3) * 16;   // S: q-tile base; PV: d-tile base
    const int wn = warp >> 2;         // 0/1
    const int n0 = wn * 32;           // S: key base; PV: q-col base

    const int bh = blockIdx.y;
    const int b = bh >> 4, h = bh & 15;
    const int q0 = blockIdx.x * 64;
    const size_t hb = (size_t)b * SEQ * DMODEL + (size_t)h * DHEAD;

    // cp.async coords for 64x64 tile: 1024 chunks, 4/thread
    const int krow = tid >> 4;            // 0..15
    const int kcol = (tid & 15) * 4;      // 0..60
    const float* Kg = K + hb + (size_t)krow * DMODEL + kcol;
    const float* Vg = V + hb + (size_t)krow * DMODEL + kcol;

    // ---- stage scaled Q (tf32) into Ss, extract register fragments ----
    {
        const int trow = tid >> 2;
        const int tc = (tid & 3) * 16;
        const float* Qp = Q + hb + (size_t)(q0 + trow) * DMODEL + tc;
#pragma unroll
        for (int i = 0; i < 4; i++) {
            float4 v = *(const float4*)(Qp + 4 * i);
            *(uint4*)&Ss[trow * SS_W + tc + 4 * i] =
                make_uint4(f2t(v.x * ATTN_SCALE), f2t(v.y * ATTN_SCALE),
                           f2t(v.z * ATTN_SCALE), f2t(v.w * ATTN_SCALE));
        }
    }
    if (tid < 64) { mrow2[tid] = -INFINITY; lrow[tid] = 0.f; }

    // prologue: stage jb=0 into buf 0
#pragma unroll
    for (int k = 0; k < 4; k++) {
        cp16(&KsBuf[(krow + 16 * k) * KS_W + kcol], Kg + (size_t)(16 * k) * DMODEL);
        cp16(&VsBuf[(krow + 16 * k) * VS_W + kcol], Vg + (size_t)(16 * k) * DMODEL);
    }
    cp_commit();
    __syncthreads();

    unsigned qf[8][4];
#pragma unroll
    for (int ks = 0; ks < 8; ks++) {
        qf[ks][0] = Ss[(m0 + qd) * SS_W + ks * 8 + r];
        qf[ks][1] = Ss[(m0 + qd + 8) * SS_W + ks * 8 + r];
        qf[ks][2] = Ss[(m0 + qd) * SS_W + ks * 8 + r + 4];
        qf[ks][3] = Ss[(m0 + qd + 8) * SS_W + ks * 8 + r + 4];
    }

    float oacc[4][4];
#pragma unroll
    for (int nt = 0; nt < 4; nt++)
#pragma unroll
        for (int i = 0; i < 4; i++) oacc[nt][i] = 0.f;

#pragma unroll 1
    for (int jb = 0; jb < SEQ / 64; jb++) {
        const int buf = jb & 1;
        if (jb + 1 < SEQ / 64) {
            const float* Kn = Kg + (size_t)((jb + 1) * 64) * DMODEL;
            const float* Vn = Vg + (size_t)((jb + 1) * 64) * DMODEL;
            float* Kd = KsBuf + (buf ^ 1) * KS_SZ;
            float* Vd = VsBuf + (buf ^ 1) * VS_SZ;
#pragma unroll
            for (int k = 0; k < 4; k++) {
                cp16(&Kd[(krow + 16 * k) * KS_W + kcol], Kn + (size_t)(16 * k) * DMODEL);
                cp16(&Vd[(krow + 16 * k) * VS_W + kcol], Vn + (size_t)(16 * k) * DMODEL);
            }
            cp_commit();
            cp_wait1();
        } else {
            cp_wait0();
        }
        __syncthreads();  // SYNC_A: current K/V visible; prev PV reads done

        const float* Ksb = KsBuf + buf * KS_SZ;
        const float* Vsb = VsBuf + buf * VS_SZ;
        const float* mrowC = mrow2 + (jb & 1) * 64;
        float* mrowN = mrow2 + ((jb + 1) & 1) * 64;

        // ---- S = Q K^T ----
        float sa[4][4];
#pragma unroll
        for (int nt = 0; nt < 4; nt++)
#pragma unroll
            for (int i = 0; i < 4; i++) sa[nt][i] = 0.f;

#pragma unroll
        for (int ks = 0; ks < 8; ks++) {
#pragma unroll
            for (int nt = 0; nt < 4; nt++) {
                unsigned bf[2];
                bf[0] = f2t(Ksb[(n0 + nt * 8 + qd) * KS_W + ks * 8 + r]);
                bf[1] = f2t(Ksb[(n0 + nt * 8 + qd) * KS_W + ks * 8 + r + 4]);
                mma8(sa[nt], qf[ks], bf);
            }
        }

        // ---- per-warp row max -> smem ----
        float mx0 = sa[0][0], mx1 = sa[0][2];
#pragma unroll
        for (int nt = 0; nt < 4; nt++) {
            mx0 = fmaxf(mx0, fmaxf(sa[nt][0], sa[nt][1]));
            mx1 = fmaxf(mx1, fmaxf(sa[nt][2], sa[nt][3]));
        }
        mx0 = fmaxf(mx0, __shfl_xor_sync(0xffffffffu, mx0, 1));
        mx0 = fmaxf(mx0, __shfl_xor_sync(0xffffffffu, mx0, 2));
        mx1 = fmaxf(mx1, __shfl_xor_sync(0xffffffffu, mx1, 1));
        mx1 = fmaxf(mx1, __shfl_xor_sync(0xffffffffu, mx1, 2));
        if (r == 0) {
            wmax[wn * 64 + m0 + qd] = mx0;
            wmax[wn * 64 + m0 + qd + 8] = mx1;
        }
        __syncthreads();  // SYNC_B: wmax ready

        // ---- new row max (local, redundant), exp, P store, wsum ----
        {
            float molo = mrowC[m0 + qd];
            float mohi = mrowC[m0 + qd + 8];
            float mlo = fmaxf(molo, fmaxf(wmax[m0 + qd], wmax[64 + m0 + qd]));
            float mhi = fmaxf(mohi, fmaxf(wmax[m0 + qd + 8], wmax[64 + m0 + qd + 8]));
            float s0 = 0.f, s1 = 0.f;
#pragma unroll
            for (int nt = 0; nt < 4; nt++) {
                unsigned u0 = f2t(__expf(sa[nt][0] - mlo));
                unsigned u1 = f2t(__expf(sa[nt][1] - mlo));
                unsigned u2 = f2t(__expf(sa[nt][2] - mhi));
                unsigned u3 = f2t(__expf(sa[nt][3] - mhi));
                s0 += __uint_as_float(u0) + __uint_as_float(u1);
                s1 += __uint_as_float(u2) + __uint_as_float(u3);
                *(uint2*)&Ss[(m0 + qd) * SS_W + n0 + nt * 8 + 2 * r] = make_uint2(u0, u1);
                *(uint2*)&Ss[(m0 + qd + 8) * SS_W + n0 + nt * 8 + 2 * r] = make_uint2(u2, u3);
            }
            s0 += __shfl_xor_sync(0xffffffffu, s0, 1);
            s0 += __shfl_xor_sync(0xffffffffu, s0, 2);
            s1 += __shfl_xor_sync(0xffffffffu, s1, 1);
            s1 += __shfl_xor_sync(0xffffffffu, s1, 2);
            if (r == 0) {
                wsum[wn * 64 + m0 + qd] = s0;
                wsum[wn * 64 + m0 + qd + 8] = s1;
            }
        }
        if (tid < 64) {
            float mo = mrowC[tid];
            mrowN[tid] = fmaxf(mo, fmaxf(wmax[tid], wmax[64 + tid]));
        }

        // ---- rescale O^T accumulators (alpha computed locally) ----
#pragma unroll
        for (int nt = 0; nt < 4; nt++) {
            int c = n0 + nt * 8 + 2 * r;
            float mo0 = mrowC[c], mo1 = mrowC[c + 1];
            float mn0 = fmaxf(mo0, fmaxf(wmax[c], wmax[64 + c]));
            float mn1 = fmaxf(mo1, fmaxf(wmax[c + 1], wmax[64 + c + 1]));
            float a0 = __expf(mo0 - mn0);
            float a1 = __expf(mo1 - mn1);
            oacc[nt][0] *= a0; oacc[nt][1] *= a1;
            oacc[nt][2] *= a0; oacc[nt][3] *= a1;
        }
        __syncthreads();  // SYNC_C: P + wsum + mrowN ready

        if (tid < 64) {
            float alpha = __expf(mrowC[tid] - mrowN[tid]);
            lrow[tid] = lrow[tid] * alpha + wsum[tid] + wsum[64 + tid];
        }

        // ---- O^T += V^T @ P^T ----
#pragma unroll
        for (int ks = 0; ks < 8; ks++) {
            unsigned av[4];
            av[0] = f2t(Vsb[(ks * 8 + r) * VS_W + m0 + qd]);
            av[1] = f2t(Vsb[(ks * 8 + r) * VS_W + m0 + qd + 8]);
            av[2] = f2t(Vsb[(ks * 8 + r + 4) * VS_W + m0 + qd]);
            av[3] = f2t(Vsb[(ks * 8 + r + 4) * VS_W + m0 + qd + 8]);
#pragma unroll
            for (int nt = 0; nt < 4; nt++) {
                unsigned bp[2];
                bp[0] = Ss[(n0 + nt * 8 + qd) * SS_W + ks * 8 + r];
                bp[1] = Ss[(n0 + nt * 8 + qd) * SS_W + ks * 8 + r + 4];
                mma8(oacc[nt], av, bp);
            }
        }
        __syncthreads();  // SYNC_D: PV reads done before next-iter cp.async overwrite
    }

    // ---- epilogue: normalize, write O ----
    float* Op = O + hb + (size_t)q0 * DMODEL;
#pragma unroll
    for (int nt = 0; nt < 4; nt++) {
        int c0 = n0 + nt * 8 + 2 * r;
        float i0 = 1.f / lrow[c0];
        float i1 = 1.f / lrow[c0 + 1];
        int d0 = m0 + qd;
        Op[(size_t)c0 * DMODEL + d0]           = oacc[nt][0] * i0;
        Op[(size_t)(c0 + 1) * DMODEL + d0]     = oacc[nt][1] * i1;
        Op[(size_t)c0 * DMODEL + d0 + 8]       = oacc[nt][2] * i0;
        Op[(size_t)(c0 + 1) * DMODEL + d0 + 8] = oacc[nt][3] * i1;
    }
}

extern "C" void kernel_launch(void* const* d_in, const int* in_sizes, int n_in,
                              void* d_out, int out_size) {
    const float* x  = (const float*)d_in[0];
    const float* Wq = (const float*)d_in[1];
    const float* Wk = (const float*)d_in[2];
    const float* Wv = (const float*)d_in[3];
    const float* Wo = (const float*)d_in[4];
    const float* bo = (const float*)d_in[5];
    float* out = (float*)d_out;

    void *pQ, *pK, *pV, *pO;
    cudaGetSymbolAddress(&pQ, g_Q);
    cudaGetSymbolAddress(&pK, g_K);
    cudaGetSymbolAddress(&pV, g_V);
    cudaGetSymbolAddress(&pO, g_O);

    const int attn_smem = ATTN_SMEM_WORDS * (int)sizeof(float);  // 90880 B
    cudaFuncSetAttribute(attn_tf32, cudaFuncAttributeMaxDynamicSharedMemorySize,
                         attn_smem);

    dim3 ggrid(DMODEL / 128, MTOT / 128, 3);  // (8, 64, 3)
    gemm_qkv<<<ggrid, 256>>>(x, Wq, Wk, Wv, (float*)pQ, (float*)pK, (float*)pV);

    dim3 agrid(SEQ / 64, BSZ * NHEADS);       // (32, 64)
    attn_tf32<<<agrid, 256, attn_smem>>>((const float*)pQ, (const float*)pK,
                                         (const float*)pV, (float*)pO);

    dim3 ogrid(DMODEL / 128, MTOT / 128, 1);
    gemm_out<<<ogrid, 256>>>((const float*)pO, Wo, bo, out);
}

// round 11
// speedup vs baseline: 3.5212x; 1.0077x over previous
#include <cuda_runtime.h>
#include <math.h>

#define BSZ 4
#define SEQ 2048
#define DMODEL 1024
#define NHEADS 16
#define DHEAD 64
#define MTOT (BSZ * SEQ)          // 8192
#define ATTN_SCALE 0.125f

// ---------------- scratch ----------------
__device__ float g_Q[(size_t)MTOT * DMODEL];
__device__ float g_K[(size_t)MTOT * DMODEL];
__device__ float g_V[(size_t)MTOT * DMODEL];
__device__ float g_O[(size_t)MTOT * DMODEL];
__device__ float g_X[(size_t)MTOT * DMODEL];          // tf32-rounded x
__device__ float g_Wqt[(size_t)DMODEL * DMODEL];      // tf32-rounded weights
__device__ float g_Wkt[(size_t)DMODEL * DMODEL];
__device__ float g_Wvt[(size_t)DMODEL * DMODEL];
__device__ float g_Wot[(size_t)DMODEL * DMODEL];

// ---------------- helpers ----------------
__device__ __forceinline__ unsigned f2t(float x) {
    unsigned u;
    asm("cvt.rna.tf32.f32 %0, %1;" : "=r"(u) : "f"(x));
    return u;
}

__device__ __forceinline__ void mma8(float* c, const unsigned* a, const unsigned* b) {
    asm volatile(
        "mma.sync.aligned.m16n8k8.row.col.f32.tf32.tf32.f32 "
        "{%0,%1,%2,%3}, {%4,%5,%6,%7}, {%8,%9}, {%0,%1,%2,%3};"
        : "+f"(c[0]), "+f"(c[1]), "+f"(c[2]), "+f"(c[3])
        : "r"(a[0]), "r"(a[1]), "r"(a[2]), "r"(a[3]), "r"(b[0]), "r"(b[1]));
}

__device__ __forceinline__ void cp16(float* dst, const float* src) {
    unsigned d = (unsigned)__cvta_generic_to_shared(dst);
    asm volatile("cp.async.cg.shared.global [%0], [%1], 16;" :: "r"(d), "l"(src));
}
__device__ __forceinline__ void cp_commit() {
    asm volatile("cp.async.commit_group;");
}
__device__ __forceinline__ void cp_wait1() {
    asm volatile("cp.async.wait_group 1;");
}
__device__ __forceinline__ void cp_wait0() {
    asm volatile("cp.async.wait_group 0;");
}

// ---------------- tf32 pre-rounding pass ----------------
__global__ __launch_bounds__(256) void cvt_tf32_kernel(const float* __restrict__ src,
                                                       float* __restrict__ dst) {
    int i = blockIdx.x * blockDim.x + threadIdx.x;
    float4 v = ((const float4*)src)[i];
    float4 o;
    o.x = __uint_as_float(f2t(v.x));
    o.y = __uint_as_float(f2t(v.y));
    o.z = __uint_as_float(f2t(v.z));
    o.w = __uint_as_float(f2t(v.w));
    ((float4*)dst)[i] = o;
}

// ---------------- tf32 GEMM: C[M,1024] = A @ W^T ----------------
// A and W are PRE-ROUNDED tf32 values stored as fp32. Fragment loads are
// plain bit-copies (no cvt). Epilogue modes:
//   0: raw fp32 + bias (final output)
//   1: tf32-round    (K, V)
//   2: tf32-round of acc*ATTN_SCALE (Q)
__device__ __forceinline__ void gemm_body(const float* __restrict__ A,
                                          const float* __restrict__ W,
                                          const float* __restrict__ bias,
                                          float* __restrict__ C,
                                          int mode) {
    __shared__ float As[2][128 * 20];
    __shared__ float Bs[2][128 * 20];

    const int tid = threadIdx.x;
    const int warp = tid >> 5, lane = tid & 31;
    const int qd = lane >> 2, r = lane & 3;
    const int wm = (warp & 1) * 64;
    const int wn = (warp >> 1) * 32;
    const int row0 = blockIdx.y * 128;
    const int col0 = blockIdx.x * 128;

    const int cr = tid >> 2;            // 0..63
    const int cc = (tid & 3) * 4;       // 0,4,8,12
    const float* Ap0 = A + (size_t)(row0 + cr) * DMODEL + cc;
    const float* Ap1 = A + (size_t)(row0 + cr + 64) * DMODEL + cc;
    const float* Wp0 = W + (size_t)(col0 + cr) * DMODEL + cc;
    const float* Wp1 = W + (size_t)(col0 + cr + 64) * DMODEL + cc;
    const int so0 = cr * 20 + cc;
    const int so1 = (cr + 64) * 20 + cc;

    float acc[4][4][4];
#pragma unroll
    for (int mt = 0; mt < 4; mt++)
#pragma unroll
        for (int nt = 0; nt < 4; nt++)
#pragma unroll
            for (int i = 0; i < 4; i++) acc[mt][nt][i] = 0.f;

    cp16(&As[0][so0], Ap0);
    cp16(&As[0][so1], Ap1);
    cp16(&Bs[0][so0], Wp0);
    cp16(&Bs[0][so1], Wp1);
    cp_commit();

    int buf = 0;
#pragma unroll 1
    for (int bk = 0; bk < DMODEL; bk += 16, buf ^= 1) {
        if (bk + 16 < DMODEL) {
            cp16(&As[buf ^ 1][so0], Ap0 + bk + 16);
            cp16(&As[buf ^ 1][so1], Ap1 + bk + 16);
            cp16(&Bs[buf ^ 1][so0], Wp0 + bk + 16);
            cp16(&Bs[buf ^ 1][so1], Wp1 + bk + 16);
            cp_commit();
            cp_wait1();
        } else {
            cp_wait0();
        }
        __syncthreads();

        const float* Ab = As[buf];
        const float* Bb = Bs[buf];
#pragma unroll
        for (int ks = 0; ks < 2; ks++) {
            unsigned af[4][4], bf[4][2];
#pragma unroll
            for (int mt = 0; mt < 4; mt++) {
                int mr = wm + mt * 16;
                af[mt][0] = __float_as_uint(Ab[(mr + qd) * 20 + ks * 8 + r]);
                af[mt][1] = __float_as_uint(Ab[(mr + qd + 8) * 20 + ks * 8 + r]);
                af[mt][2] = __float_as_uint(Ab[(mr + qd) * 20 + ks * 8 + r + 4]);
                af[mt][3] = __float_as_uint(Ab[(mr + qd + 8) * 20 + ks * 8 + r + 4]);
            }
#pragma unroll
            for (int nt = 0; nt < 4; nt++) {
                int nc = wn + nt * 8;
                bf[nt][0] = __float_as_uint(Bb[(nc + qd) * 20 + ks * 8 + r]);
                bf[nt][1] = __float_as_uint(Bb[(nc + qd) * 20 + ks * 8 + r + 4]);
            }
#pragma unroll
            for (int mt = 0; mt < 4; mt++)
#pragma unroll
                for (int nt = 0; nt < 4; nt++)
                    mma8(acc[mt][nt], af[mt], bf[nt]);
        }
        __syncthreads();
    }

    if (mode == 0) {
#pragma unroll
        for (int mt = 0; mt < 4; mt++) {
            int rlo = row0 + wm + mt * 16 + qd;
#pragma unroll
            for (int nt = 0; nt < 4; nt++) {
                int col = col0 + wn + nt * 8 + 2 * r;
                float b0 = bias[col];
                float b1 = bias[col + 1];
                float2 lo = make_float2(acc[mt][nt][0] + b0, acc[mt][nt][1] + b1);
                float2 hi = make_float2(acc[mt][nt][2] + b0, acc[mt][nt][3] + b1);
                *(float2*)&C[(size_t)rlo * DMODEL + col] = lo;
                *(float2*)&C[(size_t)(rlo + 8) * DMODEL + col] = hi;
            }
        }
    } else {
        const float s = (mode == 2) ? ATTN_SCALE : 1.f;
#pragma unroll
        for (int mt = 0; mt < 4; mt++) {
            int rlo = row0 + wm + mt * 16 + qd;
#pragma unroll
            for (int nt = 0; nt < 4; nt++) {
                int col = col0 + wn + nt * 8 + 2 * r;
                float2 lo = make_float2(__uint_as_float(f2t(acc[mt][nt][0] * s)),
                                        __uint_as_float(f2t(acc[mt][nt][1] * s)));
                float2 hi = make_float2(__uint_as_float(f2t(acc[mt][nt][2] * s)),
                                        __uint_as_float(f2t(acc[mt][nt][3] * s)));
                *(float2*)&C[(size_t)rlo * DMODEL + col] = lo;
                *(float2*)&C[(size_t)(rlo + 8) * DMODEL + col] = hi;
            }
        }
    }
}

__global__ __launch_bounds__(256, 2) void gemm_qkv(const float* __restrict__ x,
                                                   const float* __restrict__ Wq,
                                                   const float* __restrict__ Wk,
                                                   const float* __restrict__ Wv,
                                                   float* __restrict__ Qo,
                                                   float* __restrict__ Ko,
                                                   float* __restrict__ Vo) {
    const float* W = (blockIdx.z == 0) ? Wq : (blockIdx.z == 1) ? Wk : Wv;
    float* C = (blockIdx.z == 0) ? Qo : (blockIdx.z == 1) ? Ko : Vo;
    gemm_body(x, W, nullptr, C, (blockIdx.z == 0) ? 2 : 1);
}

__global__ __launch_bounds__(256, 2) void gemm_out(const float* __restrict__ A,
                                                   const float* __restrict__ W,
                                                   const float* __restrict__ bias,
                                                   float* __restrict__ C) {
    gemm_body(A, W, bias, C, 0);
}

// ---------------- tf32 flash attention ----------------
// Q/K/V in gmem are already tf32-rounded (Q also pre-scaled). All fragment
// loads are bit-copies; only the softmax P values get rounded (for l-sum
// consistency) and the output O is rounded for gemm_out.
#define KS_W 68
#define VS_W 72
#define SS_W 68
#define KS_SZ (64 * KS_W)  // 4352
#define VS_SZ (64 * VS_W)  // 4608
#define OFF_V (2 * KS_SZ)
#define OFF_S (2 * KS_SZ + 2 * VS_SZ)
#define OFF_M (OFF_S + 64 * SS_W)
#define OFF_L (OFF_M + 128)
#define OFF_WM (OFF_L + 64)
#define OFF_WS (OFF_WM + 128)
#define ATTN_SMEM_WORDS (OFF_WS + 128)   // 22720 -> 90880 B

__global__ __launch_bounds__(256, 2) void attn_tf32(const float* __restrict__ Q,
                                                    const float* __restrict__ K,
                                                    const float* __restrict__ V,
                                                    float* __restrict__ O) {
    extern __shared__ float smf[];
    float* KsBuf = smf;                  // [2][KS_SZ]
    float* VsBuf = smf + OFF_V;          // [2][VS_SZ]
    unsigned* Ss = (unsigned*)(smf + OFF_S);
    float* mrow2 = smf + OFF_M;          // ping-pong [2][64]
    float* lrow = smf + OFF_L;
    float* wmax = smf + OFF_WM;          // [2][64]
    float* wsum = smf + OFF_WS;          // [2][64]

    const int tid = threadIdx.x;
    const int warp = tid >> 5, lane = tid & 31;
    const int qd = lane >> 2, r = lane & 3;
    const int m0 = (warp & 3) * 16;   // S: q-tile base; PV: d-tile base
    const int wn = warp >> 2;         // 0/1
    const int n0 = wn * 32;           // S: key base; PV: q-col base

    const int bh = blockIdx.y;
    const int b = bh >> 4, h = bh & 15;
    const int q0 = blockIdx.x * 64;
    const size_t hb = (size_t)b * SEQ * DMODEL + (size_t)h * DHEAD;

    const int krow = tid >> 4;            // 0..15
    const int kcol = (tid & 15) * 4;      // 0..60
    const float* Kg = K + hb + (size_t)krow * DMODEL + kcol;
    const float* Vg = V + hb + (size_t)krow * DMODEL + kcol;

    // ---- stage Q (already scaled+rounded) into Ss: plain bit-copy ----
    {
        const int trow = tid >> 2;
        const int tc = (tid & 3) * 16;
        const float* Qp = Q + hb + (size_t)(q0 + trow) * DMODEL + tc;
#pragma unroll
        for (int i = 0; i < 4; i++)
            *(uint4*)&Ss[trow * SS_W + tc + 4 * i] = *(const uint4*)(Qp + 4 * i);
    }
    if (tid < 64) { mrow2[tid] = -INFINITY; lrow[tid] = 0.f; }

    // prologue: stage jb=0 into buf 0
#pragma unroll
    for (int k = 0; k < 4; k++) {
        cp16(&KsBuf[(krow + 16 * k) * KS_W + kcol], Kg + (size_t)(16 * k) * DMODEL);
        cp16(&VsBuf[(krow + 16 * k) * VS_W + kcol], Vg + (size_t)(16 * k) * DMODEL);
    }
    cp_commit();
    __syncthreads();

    unsigned qf[8][4];
#pragma unroll
    for (int ks = 0; ks < 8; ks++) {
        qf[ks][0] = Ss[(m0 + qd) * SS_W + ks * 8 + r];
        qf[ks][1] = Ss[(m0 + qd + 8) * SS_W + ks * 8 + r];
        qf[ks][2] = Ss[(m0 + qd) * SS_W + ks * 8 + r + 4];
        qf[ks][3] = Ss[(m0 + qd + 8) * SS_W + ks * 8 + r + 4];
    }

    float oacc[4][4];
#pragma unroll
    for (int nt = 0; nt < 4; nt++)
#pragma unroll
        for (int i = 0; i < 4; i++) oacc[nt][i] = 0.f;

#pragma unroll 1
    for (int jb = 0; jb < SEQ / 64; jb++) {
        const int buf = jb & 1;
        if (jb + 1 < SEQ / 64) {
            const float* Kn = Kg + (size_t)((jb + 1) * 64) * DMODEL;
            const float* Vn = Vg + (size_t)((jb + 1) * 64) * DMODEL;
            float* Kd = KsBuf + (buf ^ 1) * KS_SZ;
            float* Vd = VsBuf + (buf ^ 1) * VS_SZ;
#pragma unroll
            for (int k = 0; k < 4; k++) {
                cp16(&Kd[(krow + 16 * k) * KS_W + kcol], Kn + (size_t)(16 * k) * DMODEL);
                cp16(&Vd[(krow + 16 * k) * VS_W + kcol], Vn + (size_t)(16 * k) * DMODEL);
            }
            cp_commit();
            cp_wait1();
        } else {
            cp_wait0();
        }
        __syncthreads();  // SYNC_A

        const float* Ksb = KsBuf + buf * KS_SZ;
        const float* Vsb = VsBuf + buf * VS_SZ;
        const float* mrowC = mrow2 + (jb & 1) * 64;
        float* mrowN = mrow2 + ((jb + 1) & 1) * 64;

        // ---- S = Q K^T (K pre-rounded: bit-copy fragments) ----
        float sa[4][4];
#pragma unroll
        for (int nt = 0; nt < 4; nt++)
#pragma unroll
            for (int i = 0; i < 4; i++) sa[nt][i] = 0.f;

#pragma unroll
        for (int ks = 0; ks < 8; ks++) {
#pragma unroll
            for (int nt = 0; nt < 4; nt++) {
                unsigned bf[2];
                bf[0] = __float_as_uint(Ksb[(n0 + nt * 8 + qd) * KS_W + ks * 8 + r]);
                bf[1] = __float_as_uint(Ksb[(n0 + nt * 8 + qd) * KS_W + ks * 8 + r + 4]);
                mma8(sa[nt], qf[ks], bf);
            }
        }

        // ---- per-warp row max -> smem ----
        float mx0 = sa[0][0], mx1 = sa[0][2];
#pragma unroll
        for (int nt = 0; nt < 4; nt++) {
            mx0 = fmaxf(mx0, fmaxf(sa[nt][0], sa[nt][1]));
            mx1 = fmaxf(mx1, fmaxf(sa[nt][2], sa[nt][3]));
        }
        mx0 = fmaxf(mx0, __shfl_xor_sync(0xffffffffu, mx0, 1));
        mx0 = fmaxf(mx0, __shfl_xor_sync(0xffffffffu, mx0, 2));
        mx1 = fmaxf(mx1, __shfl_xor_sync(0xffffffffu, mx1, 1));
        mx1 = fmaxf(mx1, __shfl_xor_sync(0xffffffffu, mx1, 2));
        if (r == 0) {
            wmax[wn * 64 + m0 + qd] = mx0;
            wmax[wn * 64 + m0 + qd + 8] = mx1;
        }
        __syncthreads();  // SYNC_B

        // ---- exp, P store (rounded), wsum ----
        {
            float molo = mrowC[m0 + qd];
            float mohi = mrowC[m0 + qd + 8];
            float mlo = fmaxf(molo, fmaxf(wmax[m0 + qd], wmax[64 + m0 + qd]));
            float mhi = fmaxf(mohi, fmaxf(wmax[m0 + qd + 8], wmax[64 + m0 + qd + 8]));
            float s0 = 0.f, s1 = 0.f;
#pragma unroll
            for (int nt = 0; nt < 4; nt++) {
                unsigned u0 = f2t(__expf(sa[nt][0] - mlo));
                unsigned u1 = f2t(__expf(sa[nt][1] - mlo));
                unsigned u2 = f2t(__expf(sa[nt][2] - mhi));
                unsigned u3 = f2t(__expf(sa[nt][3] - mhi));
                s0 += __uint_as_float(u0) + __uint_as_float(u1);
                s1 += __uint_as_float(u2) + __uint_as_float(u3);
                *(uint2*)&Ss[(m0 + qd) * SS_W + n0 + nt * 8 + 2 * r] = make_uint2(u0, u1);
                *(uint2*)&Ss[(m0 + qd + 8) * SS_W + n0 + nt * 8 + 2 * r] = make_uint2(u2, u3);
            }
            s0 += __shfl_xor_sync(0xffffffffu, s0, 1);
            s0 += __shfl_xor_sync(0xffffffffu, s0, 2);
            s1 += __shfl_xor_sync(0xffffffffu, s1, 1);
            s1 += __shfl_xor_sync(0xffffffffu, s1, 2);
            if (r == 0) {
                wsum[wn * 64 + m0 + qd] = s0;
                wsum[wn * 64 + m0 + qd + 8] = s1;
            }
        }
        if (tid < 64) {
            float mo = mrowC[tid];
            mrowN[tid] = fmaxf(mo, fmaxf(wmax[tid], wmax[64 + tid]));
        }

        // ---- rescale O^T accumulators (alpha computed locally) ----
#pragma unroll
        for (int nt = 0; nt < 4; nt++) {
            int c = n0 + nt * 8 + 2 * r;
            float mo0 = mrowC[c], mo1 = mrowC[c + 1];
            float mn0 = fmaxf(mo0, fmaxf(wmax[c], wmax[64 + c]));
            float mn1 = fmaxf(mo1, fmaxf(wmax[c + 1], wmax[64 + c + 1]));
            float a0 = __expf(mo0 - mn0);
            float a1 = __expf(mo1 - mn1);
            oacc[nt][0] *= a0; oacc[nt][1] *= a1;
            oacc[nt][2] *= a0; oacc[nt][3] *= a1;
        }
        __syncthreads();  // SYNC_C

        if (tid < 64) {
            float alpha = __expf(mrowC[tid] - mrowN[tid]);
            lrow[tid] = lrow[tid] * alpha + wsum[tid] + wsum[64 + tid];
        }

        // ---- O^T += V^T @ P^T (V pre-rounded: bit-copy fragments) ----
#pragma unroll
        for (int ks = 0; ks < 8; ks++) {
            unsigned av[4];
            av[0] = __float_as_uint(Vsb[(ks * 8 + r) * VS_W + m0 + qd]);
            av[1] = __float_as_uint(Vsb[(ks * 8 + r) * VS_W + m0 + qd + 8]);
            av[2] = __float_as_uint(Vsb[(ks * 8 + r + 4) * VS_W + m0 + qd]);
            av[3] = __float_as_uint(Vsb[(ks * 8 + r + 4) * VS_W + m0 + qd + 8]);
#pragma unroll
            for (int nt = 0; nt < 4; nt++) {
                unsigned bp[2];
                bp[0] = Ss[(n0 + nt * 8 + qd) * SS_W + ks * 8 + r];
                bp[1] = Ss[(n0 + nt * 8 + qd) * SS_W + ks * 8 + r + 4];
                mma8(oacc[nt], av, bp);
            }
        }
        __syncthreads();  // SYNC_D
    }

    // ---- epilogue: normalize, round for gemm_out, write O ----
    float* Op = O + hb + (size_t)q0 * DMODEL;
#pragma unroll
    for (int nt = 0; nt < 4; nt++) {
        int c0 = n0 + nt * 8 + 2 * r;
        float i0 = 1.f / lrow[c0];
        float i1 = 1.f / lrow[c0 + 1];
        int d0 = m0 + qd;
        Op[(size_t)c0 * DMODEL + d0]           = __uint_as_float(f2t(oacc[nt][0] * i0));
        Op[(size_t)(c0 + 1) * DMODEL + d0]     = __uint_as_float(f2t(oacc[nt][1] * i1));
        Op[(size_t)c0 * DMODEL + d0 + 8]       = __uint_as_float(f2t(oacc[nt][2] * i0));
        Op[(size_t)(c0 + 1) * DMODEL + d0 + 8] = __uint_as_float(f2t(oacc[nt][3] * i1));
    }
}

extern "C" void kernel_launch(void* const* d_in, const int* in_sizes, int n_in,
                              void* d_out, int out_size) {
    const float* x  = (const float*)d_in[0];
    const float* Wq = (const float*)d_in[1];
    const float* Wk = (const float*)d_in[2];
    const float* Wv = (const float*)d_in[3];
    const float* Wo = (const float*)d_in[4];
    const float* bo = (const float*)d_in[5];
    float* out = (float*)d_out;

    void *pQ, *pK, *pV, *pO, *pX, *pWq, *pWk, *pWv, *pWo;
    cudaGetSymbolAddress(&pQ, g_Q);
    cudaGetSymbolAddress(&pK, g_K);
    cudaGetSymbolAddress(&pV, g_V);
    cudaGetSymbolAddress(&pO, g_O);
    cudaGetSymbolAddress(&pX, g_X);
    cudaGetSymbolAddress(&pWq, g_Wqt);
    cudaGetSymbolAddress(&pWk, g_Wkt);
    cudaGetSymbolAddress(&pWv, g_Wvt);
    cudaGetSymbolAddress(&pWo, g_Wot);

    const int attn_smem = ATTN_SMEM_WORDS * (int)sizeof(float);  // 90880 B
    cudaFuncSetAttribute(attn_tf32, cudaFuncAttributeMaxDynamicSharedMemorySize,
                         attn_smem);

    // pre-round inputs to tf32 (numerics-identical to cvt-at-fragment-load)
    const int XB = (MTOT * DMODEL / 4) / 256;     // 8192
    const int WB = (DMODEL * DMODEL / 4) / 256;   // 1024
    cvt_tf32_kernel<<<XB, 256>>>(x, (float*)pX);
    cvt_tf32_kernel<<<WB, 256>>>(Wq, (float*)pWq);
    cvt_tf32_kernel<<<WB, 256>>>(Wk, (float*)pWk);
    cvt_tf32_kernel<<<WB, 256>>>(Wv, (float*)pWv);
    cvt_tf32_kernel<<<WB, 256>>>(Wo, (float*)pWo);

    dim3 ggrid(DMODEL / 128, MTOT / 128, 3);  // (8, 64, 3)
    gemm_qkv<<<ggrid, 256>>>((const float*)pX, (const float*)pWq,
                             (const float*)pWk, (const float*)pWv,
                             (float*)pQ, (float*)pK, (float*)pV);

    dim3 agrid(SEQ / 64, BSZ * NHEADS);       // (32, 64)
    attn_tf32<<<agrid, 256, attn_smem>>>((const float*)pQ, (const float*)pK,
                                         (const float*)pV, (float*)pO);

    dim3 ogrid(DMODEL / 128, MTOT / 128, 1);
    gemm_out<<<ogrid, 256>>>((const float*)pO, (const float*)pWo, bo, out);
}

// round 15
// speedup vs baseline: 3.8580x; 1.0956x over previous
#include <cuda_runtime.h>
#include <math.h>

#define BSZ 4
#define SEQ 2048
#define DMODEL 1024
#define NHEADS 16
#define DHEAD 64
#define MTOT (BSZ * SEQ)          // 8192
#define ATTN_SCALE 0.125f

// ---------------- scratch ----------------
__device__ float g_Q[(size_t)MTOT * DMODEL];
__device__ float g_K[(size_t)MTOT * DMODEL];
__device__ float g_V[(size_t)MTOT * DMODEL];
__device__ float g_O[(size_t)MTOT * DMODEL];
__device__ float g_X[(size_t)MTOT * DMODEL];          // tf32-rounded x
__device__ float g_Wqt[(size_t)DMODEL * DMODEL];      // tf32-rounded weights
__device__ float g_Wkt[(size_t)DMODEL * DMODEL];
__device__ float g_Wvt[(size_t)DMODEL * DMODEL];
__device__ float g_Wot[(size_t)DMODEL * DMODEL];

// ---------------- helpers ----------------
__device__ __forceinline__ unsigned f2t(float x) {
    unsigned u;
    asm("cvt.rna.tf32.f32 %0, %1;" : "=r"(u) : "f"(x));
    return u;
}

__device__ __forceinline__ void mma8(float* c, const unsigned* a, const unsigned* b) {
    asm volatile(
        "mma.sync.aligned.m16n8k8.row.col.f32.tf32.tf32.f32 "
        "{%0,%1,%2,%3}, {%4,%5,%6,%7}, {%8,%9}, {%0,%1,%2,%3};"
        : "+f"(c[0]), "+f"(c[1]), "+f"(c[2]), "+f"(c[3])
        : "r"(a[0]), "r"(a[1]), "r"(a[2]), "r"(a[3]), "r"(b[0]), "r"(b[1]));
}

__device__ __forceinline__ void cp16(float* dst, const float* src) {
    unsigned d = (unsigned)__cvta_generic_to_shared(dst);
    asm volatile("cp.async.cg.shared.global [%0], [%1], 16;" :: "r"(d), "l"(src));
}
__device__ __forceinline__ void cp_commit() {
    asm volatile("cp.async.commit_group;");
}
__device__ __forceinline__ void cp_wait1() {
    asm volatile("cp.async.wait_group 1;");
}
__device__ __forceinline__ void cp_wait0() {
    asm volatile("cp.async.wait_group 0;");
}

// ---------------- tf32 pre-rounding pass ----------------
__global__ __launch_bounds__(256) void cvt_tf32_kernel(const float* __restrict__ src,
                                                       float* __restrict__ dst) {
    int i = blockIdx.x * blockDim.x + threadIdx.x;
    float4 v = ((const float4*)src)[i];
    float4 o;
    o.x = __uint_as_float(f2t(v.x));
    o.y = __uint_as_float(f2t(v.y));
    o.z = __uint_as_float(f2t(v.z));
    o.w = __uint_as_float(f2t(v.w));
    ((float4*)dst)[i] = o;
}

// ---------------- tf32 GEMM: C[M,1024] = A @ W^T ----------------
// A and W PRE-ROUNDED tf32 stored as fp32; fragment loads are bit-copies.
// modes: 0 raw+bias; 1 tf32-round; 2 tf32-round of acc*ATTN_SCALE.
__device__ __forceinline__ void gemm_body(const float* __restrict__ A,
                                          const float* __restrict__ W,
                                          const float* __restrict__ bias,
                                          float* __restrict__ C,
                                          int mode) {
    __shared__ float As[2][128 * 20];
    __shared__ float Bs[2][128 * 20];

    const int tid = threadIdx.x;
    const int warp = tid >> 5, lane = tid & 31;
    const int qd = lane >> 2, r = lane & 3;
    const int wm = (warp & 1) * 64;
    const int wn = (warp >> 1) * 32;
    const int row0 = blockIdx.y * 128;
    const int col0 = blockIdx.x * 128;

    const int cr = tid >> 2;
    const int cc = (tid & 3) * 4;
    const float* Ap0 = A + (size_t)(row0 + cr) * DMODEL + cc;
    const float* Ap1 = A + (size_t)(row0 + cr + 64) * DMODEL + cc;
    const float* Wp0 = W + (size_t)(col0 + cr) * DMODEL + cc;
    const float* Wp1 = W + (size_t)(col0 + cr + 64) * DMODEL + cc;
    const int so0 = cr * 20 + cc;
    const int so1 = (cr + 64) * 20 + cc;

    float acc[4][4][4];
#pragma unroll
    for (int mt = 0; mt < 4; mt++)
#pragma unroll
        for (int nt = 0; nt < 4; nt++)
#pragma unroll
            for (int i = 0; i < 4; i++) acc[mt][nt][i] = 0.f;

    cp16(&As[0][so0], Ap0);
    cp16(&As[0][so1], Ap1);
    cp16(&Bs[0][so0], Wp0);
    cp16(&Bs[0][so1], Wp1);
    cp_commit();

    int buf = 0;
#pragma unroll 1
    for (int bk = 0; bk < DMODEL; bk += 16, buf ^= 1) {
        if (bk + 16 < DMODEL) {
            cp16(&As[buf ^ 1][so0], Ap0 + bk + 16);
            cp16(&As[buf ^ 1][so1], Ap1 + bk + 16);
            cp16(&Bs[buf ^ 1][so0], Wp0 + bk + 16);
            cp16(&Bs[buf ^ 1][so1], Wp1 + bk + 16);
            cp_commit();
            cp_wait1();
        } else {
            cp_wait0();
        }
        __syncthreads();

        const float* Ab = As[buf];
        const float* Bb = Bs[buf];
#pragma unroll
        for (int ks = 0; ks < 2; ks++) {
            unsigned af[4][4], bf[4][2];
#pragma unroll
            for (int mt = 0; mt < 4; mt++) {
                int mr = wm + mt * 16;
                af[mt][0] = __float_as_uint(Ab[(mr + qd) * 20 + ks * 8 + r]);
                af[mt][1] = __float_as_uint(Ab[(mr + qd + 8) * 20 + ks * 8 + r]);
                af[mt][2] = __float_as_uint(Ab[(mr + qd) * 20 + ks * 8 + r + 4]);
                af[mt][3] = __float_as_uint(Ab[(mr + qd + 8) * 20 + ks * 8 + r + 4]);
            }
#pragma unroll
            for (int nt = 0; nt < 4; nt++) {
                int nc = wn + nt * 8;
                bf[nt][0] = __float_as_uint(Bb[(nc + qd) * 20 + ks * 8 + r]);
                bf[nt][1] = __float_as_uint(Bb[(nc + qd) * 20 + ks * 8 + r + 4]);
            }
#pragma unroll
            for (int mt = 0; mt < 4; mt++)
#pragma unroll
                for (int nt = 0; nt < 4; nt++)
                    mma8(acc[mt][nt], af[mt], bf[nt]);
        }
        __syncthreads();
    }

    if (mode == 0) {
#pragma unroll
        for (int mt = 0; mt < 4; mt++) {
            int rlo = row0 + wm + mt * 16 + qd;
#pragma unroll
            for (int nt = 0; nt < 4; nt++) {
                int col = col0 + wn + nt * 8 + 2 * r;
                float b0 = bias[col];
                float b1 = bias[col + 1];
                float2 lo = make_float2(acc[mt][nt][0] + b0, acc[mt][nt][1] + b1);
                float2 hi = make_float2(acc[mt][nt][2] + b0, acc[mt][nt][3] + b1);
                *(float2*)&C[(size_t)rlo * DMODEL + col] = lo;
                *(float2*)&C[(size_t)(rlo + 8) * DMODEL + col] = hi;
            }
        }
    } else {
        const float s = (mode == 2) ? ATTN_SCALE : 1.f;
#pragma unroll
        for (int mt = 0; mt < 4; mt++) {
            int rlo = row0 + wm + mt * 16 + qd;
#pragma unroll
            for (int nt = 0; nt < 4; nt++) {
                int col = col0 + wn + nt * 8 + 2 * r;
                float2 lo = make_float2(__uint_as_float(f2t(acc[mt][nt][0] * s)),
                                        __uint_as_float(f2t(acc[mt][nt][1] * s)));
                float2 hi = make_float2(__uint_as_float(f2t(acc[mt][nt][2] * s)),
                                        __uint_as_float(f2t(acc[mt][nt][3] * s)));
                *(float2*)&C[(size_t)rlo * DMODEL + col] = lo;
                *(float2*)&C[(size_t)(rlo + 8) * DMODEL + col] = hi;
            }
        }
    }
}

__global__ __launch_bounds__(256, 2) void gemm_qkv(const float* __restrict__ x,
                                                   const float* __restrict__ Wq,
                                                   const float* __restrict__ Wk,
                                                   const float* __restrict__ Wv,
                                                   float* __restrict__ Qo,
                                                   float* __restrict__ Ko,
                                                   float* __restrict__ Vo) {
    const float* W = (blockIdx.z == 0) ? Wq : (blockIdx.z == 1) ? Wk : Wv;
    float* C = (blockIdx.z == 0) ? Qo : (blockIdx.z == 1) ? Ko : Vo;
    gemm_body(x, W, nullptr, C, (blockIdx.z == 0) ? 2 : 1);
}

__global__ __launch_bounds__(256, 2) void gemm_out(const float* __restrict__ A,
                                                   const float* __restrict__ W,
                                                   const float* __restrict__ bias,
                                                   float* __restrict__ C) {
    gemm_body(A, W, bias, C, 0);
}

// ---------------- tf32 flash attention v2 ----------------
// CTA: 128 query rows, 256 threads (8 warps), one (b,h) slice, occ 1.
// S phase: warp w owns q-rows [w*16, w*16+16) x FULL 64 keys (m16 x n64):
//   row max/sum are warp-private (4-lane shuffles), m/l state in registers.
// PV phase: O^T = V^T @ P^T; warp grid 4(d-tile m16) x 2(q-group n64).
// 2 barriers per key-block. K/V double-buffered via cp.async.
#define KS_W 68
#define VS_W 72
#define SS_W 68
#define KS_SZ (64 * KS_W)  // 4352
#define VS_SZ (64 * VS_W)  // 4608
#define AOFF_V (2 * KS_SZ)                    // 8704
#define AOFF_S (AOFF_V + 2 * VS_SZ)           // 17920
#define AOFF_AL (AOFF_S + 128 * SS_W)         // 26624
#define AOFF_LR (AOFF_AL + 128)               // 26752
#define ATTN_SMEM_WORDS (AOFF_LR + 128)       // 26880 -> 107520 B
#define NJB (SEQ / 64)                        // 32

__global__ __launch_bounds__(256, 1) void attn_tf32(const float* __restrict__ Q,
                                                    const float* __restrict__ K,
                                                    const float* __restrict__ V,
                                                    float* __restrict__ O) {
    extern __shared__ float smf[];
    float* KsBuf = smf;                       // [2][KS_SZ]
    float* VsBuf = smf + AOFF_V;              // [2][VS_SZ]
    unsigned* Ss = (unsigned*)(smf + AOFF_S); // Q staging, then P (tf32 bits)
    float* alphaS = smf + AOFF_AL;            // [128]
    float* lrowS = smf + AOFF_LR;             // [128]

    const int tid = threadIdx.x;
    const int warp = tid >> 5, lane = tid & 31;
    const int qd = lane >> 2, r = lane & 3;
    const int m0 = warp * 16;                 // S: q-tile base (16 rows)
    const int mP0 = (warp & 3) * 16;          // PV: d-tile base
    const int nP0 = (warp >> 2) * 64;         // PV: q-col group base

    const int bh = blockIdx.y;
    const int b = bh >> 4, h = bh & 15;
    const int q0 = blockIdx.x * 128;
    const size_t hb = (size_t)b * SEQ * DMODEL + (size_t)h * DHEAD;

    // cp.async coords for 64x64 K/V tiles: 1024 chunks, 4/thread
    const int krow = tid >> 4;                // 0..15
    const int kcol = (tid & 15) * 4;          // 0..60
    const float* Kg = K + hb + (size_t)krow * DMODEL + kcol;
    const float* Vg = V + hb + (size_t)krow * DMODEL + kcol;

    // ---- stage Q (pre-scaled+rounded): 128x64, bit-copy, 8 uint4/thread ----
    {
        const float* Qb = Q + hb + (size_t)q0 * DMODEL;
#pragma unroll
        for (int i = 0; i < 8; i++) {
            int slot = tid + i * 256;         // 0..2047
            int row = slot >> 4;
            int c4 = (slot & 15) * 4;
            *(uint4*)&Ss[row * SS_W + c4] =
                *(const uint4*)(Qb + (size_t)row * DMODEL + c4);
        }
    }
    // prologue: stage jb=0 K/V into buf 0
#pragma unroll
    for (int k = 0; k < 4; k++) {
        cp16(&KsBuf[(krow + 16 * k) * KS_W + kcol], Kg + (size_t)(16 * k) * DMODEL);
        cp16(&VsBuf[(krow + 16 * k) * VS_W + kcol], Vg + (size_t)(16 * k) * DMODEL);
    }
    cp_commit();
    __syncthreads();   // Q staged (and cp.async committed)

    // Q fragments in registers (rows m0+qd, m0+qd+8)
    unsigned qf[8][4];
#pragma unroll
    for (int ks = 0; ks < 8; ks++) {
        qf[ks][0] = Ss[(m0 + qd) * SS_W + ks * 8 + r];
        qf[ks][1] = Ss[(m0 + qd + 8) * SS_W + ks * 8 + r];
        qf[ks][2] = Ss[(m0 + qd) * SS_W + ks * 8 + r + 4];
        qf[ks][3] = Ss[(m0 + qd + 8) * SS_W + ks * 8 + r + 4];
    }

    float oacc[8][4];
#pragma unroll
    for (int nt = 0; nt < 8; nt++)
#pragma unroll
        for (int i = 0; i < 4; i++) oacc[nt][i] = 0.f;

    float mrow0 = -INFINITY, mrow1 = -INFINITY;
    float lrow0 = 0.f, lrow1 = 0.f;

    int buf = 0;
#pragma unroll 1
    for (int jb = 0; jb < NJB; jb++) {
        cp_wait0();
        __syncthreads();  // B1: K/V(jb) visible; all warps done with prior PV

        // prefetch next K/V into the other buffer (its old readers are done)
        if (jb + 1 < NJB) {
            const float* Kn = Kg + (size_t)((jb + 1) * 64) * DMODEL;
            const float* Vn = Vg + (size_t)((jb + 1) * 64) * DMODEL;
            float* Kd = KsBuf + (buf ^ 1) * KS_SZ;
            float* Vd = VsBuf + (buf ^ 1) * VS_SZ;
#pragma unroll
            for (int k = 0; k < 4; k++) {
                cp16(&Kd[(krow + 16 * k) * KS_W + kcol], Kn + (size_t)(16 * k) * DMODEL);
                cp16(&Vd[(krow + 16 * k) * VS_W + kcol], Vn + (size_t)(16 * k) * DMODEL);
            }
            cp_commit();
        }

        const float* Ksb = KsBuf + buf * KS_SZ;
        const float* Vsb = VsBuf + buf * VS_SZ;

        // ---- S = Q K^T : warp m16 x n64 ----
        float sa[8][4];
#pragma unroll
        for (int nt = 0; nt < 8; nt++)
#pragma unroll
            for (int i = 0; i < 4; i++) sa[nt][i] = 0.f;

#pragma unroll
        for (int ks = 0; ks < 8; ks++) {
#pragma unroll
            for (int nt = 0; nt < 8; nt++) {
                unsigned bf[2];
                bf[0] = __float_as_uint(Ksb[(nt * 8 + qd) * KS_W + ks * 8 + r]);
                bf[1] = __float_as_uint(Ksb[(nt * 8 + qd) * KS_W + ks * 8 + r + 4]);
                mma8(sa[nt], qf[ks], bf);
            }
        }

        // ---- warp-private softmax over full row ----
        float mx0 = sa[0][0], mx1 = sa[0][2];
#pragma unroll
        for (int nt = 0; nt < 8; nt++) {
            mx0 = fmaxf(mx0, fmaxf(sa[nt][0], sa[nt][1]));
            mx1 = fmaxf(mx1, fmaxf(sa[nt][2], sa[nt][3]));
        }
        mx0 = fmaxf(mx0, __shfl_xor_sync(0xffffffffu, mx0, 1));
        mx0 = fmaxf(mx0, __shfl_xor_sync(0xffffffffu, mx0, 2));
        mx1 = fmaxf(mx1, __shfl_xor_sync(0xffffffffu, mx1, 1));
        mx1 = fmaxf(mx1, __shfl_xor_sync(0xffffffffu, mx1, 2));

        float mn0 = fmaxf(mrow0, mx0);
        float mn1 = fmaxf(mrow1, mx1);
        float a0 = __expf(mrow0 - mn0);
        float a1 = __expf(mrow1 - mn1);

        float s0 = 0.f, s1 = 0.f;
#pragma unroll
        for (int nt = 0; nt < 8; nt++) {
            unsigned u0 = f2t(__expf(sa[nt][0] - mn0));
            unsigned u1 = f2t(__expf(sa[nt][1] - mn0));
            unsigned u2 = f2t(__expf(sa[nt][2] - mn1));
            unsigned u3 = f2t(__expf(sa[nt][3] - mn1));
            s0 += __uint_as_float(u0) + __uint_as_float(u1);
            s1 += __uint_as_float(u2) + __uint_as_float(u3);
            *(uint2*)&Ss[(m0 + qd) * SS_W + nt * 8 + 2 * r] = make_uint2(u0, u1);
            *(uint2*)&Ss[(m0 + qd + 8) * SS_W + nt * 8 + 2 * r] = make_uint2(u2, u3);
        }
        s0 += __shfl_xor_sync(0xffffffffu, s0, 1);
        s0 += __shfl_xor_sync(0xffffffffu, s0, 2);
        s1 += __shfl_xor_sync(0xffffffffu, s1, 1);
        s1 += __shfl_xor_sync(0xffffffffu, s1, 2);

        lrow0 = lrow0 * a0 + s0;
        lrow1 = lrow1 * a1 + s1;
        mrow0 = mn0;
        mrow1 = mn1;
        if (r == 0) {
            alphaS[m0 + qd] = a0;
            alphaS[m0 + qd + 8] = a1;
        }
        __syncthreads();  // B2: P + alpha visible

        // ---- rescale O^T accumulators by alpha of their q-columns ----
#pragma unroll
        for (int nt = 0; nt < 8; nt++) {
            int c = nP0 + nt * 8 + 2 * r;
            float aa0 = alphaS[c];
            float aa1 = alphaS[c + 1];
            oacc[nt][0] *= aa0; oacc[nt][1] *= aa1;
            oacc[nt][2] *= aa0; oacc[nt][3] *= aa1;
        }

        // ---- O^T += V^T @ P^T : warp m16(d) x n64(q) ----
#pragma unroll
        for (int ks = 0; ks < 8; ks++) {
            unsigned av[4];
            av[0] = __float_as_uint(Vsb[(ks * 8 + r) * VS_W + mP0 + qd]);
            av[1] = __float_as_uint(Vsb[(ks * 8 + r) * VS_W + mP0 + qd + 8]);
            av[2] = __float_as_uint(Vsb[(ks * 8 + r + 4) * VS_W + mP0 + qd]);
            av[3] = __float_as_uint(Vsb[(ks * 8 + r + 4) * VS_W + mP0 + qd + 8]);
#pragma unroll
            for (int nt = 0; nt < 8; nt++) {
                unsigned bp[2];
                bp[0] = Ss[(nP0 + nt * 8 + qd) * SS_W + ks * 8 + r];
                bp[1] = Ss[(nP0 + nt * 8 + qd) * SS_W + ks * 8 + r + 4];
                mma8(oacc[nt], av, bp);
            }
        }
        buf ^= 1;
    }

    // publish lrow, then normalize + write O (rounded for gemm_out)
    if (r == 0) {
        lrowS[m0 + qd] = lrow0;
        lrowS[m0 + qd + 8] = lrow1;
    }
    __syncthreads();

    float* Op = O + hb + (size_t)q0 * DMODEL;
#pragma unroll
    for (int nt = 0; nt < 8; nt++) {
        int c0 = nP0 + nt * 8 + 2 * r;
        float i0 = 1.f / lrowS[c0];
        float i1 = 1.f / lrowS[c0 + 1];
        int d0 = mP0 + qd;
        Op[(size_t)c0 * DMODEL + d0]           = __uint_as_float(f2t(oacc[nt][0] * i0));
        Op[(size_t)(c0 + 1) * DMODEL + d0]     = __uint_as_float(f2t(oacc[nt][1] * i1));
        Op[(size_t)c0 * DMODEL + d0 + 8]       = __uint_as_float(f2t(oacc[nt][2] * i0));
        Op[(size_t)(c0 + 1) * DMODEL + d0 + 8] = __uint_as_float(f2t(oacc[nt][3] * i1));
    }
}

extern "C" void kernel_launch(void* const* d_in, const int* in_sizes, int n_in,
                              void* d_out, int out_size) {
    const float* x  = (const float*)d_in[0];
    const float* Wq = (const float*)d_in[1];
    const float* Wk = (const float*)d_in[2];
    const float* Wv = (const float*)d_in[3];
    const float* Wo = (const float*)d_in[4];
    const float* bo = (const float*)d_in[5];
    float* out = (float*)d_out;

    void *pQ, *pK, *pV, *pO, *pX, *pWq, *pWk, *pWv, *pWo;
    cudaGetSymbolAddress(&pQ, g_Q);
    cudaGetSymbolAddress(&pK, g_K);
    cudaGetSymbolAddress(&pV, g_V);
    cudaGetSymbolAddress(&pO, g_O);
    cudaGetSymbolAddress(&pX, g_X);
    cudaGetSymbolAddress(&pWq, g_Wqt);
    cudaGetSymbolAddress(&pWk, g_Wkt);
    cudaGetSymbolAddress(&pWv, g_Wvt);
    cudaGetSymbolAddress(&pWo, g_Wot);

    const int attn_smem = ATTN_SMEM_WORDS * (int)sizeof(float);  // 107520 B
    cudaFuncSetAttribute(attn_tf32, cudaFuncAttributeMaxDynamicSharedMemorySize,
                         attn_smem);

    // pre-round inputs to tf32
    const int XB = (MTOT * DMODEL / 4) / 256;     // 8192
    const int WB = (DMODEL * DMODEL / 4) / 256;   // 1024
    cvt_tf32_kernel<<<XB, 256>>>(x, (float*)pX);
    cvt_tf32_kernel<<<WB, 256>>>(Wq, (float*)pWq);
    cvt_tf32_kernel<<<WB, 256>>>(Wk, (float*)pWk);
    cvt_tf32_kernel<<<WB, 256>>>(Wv, (float*)pWv);
    cvt_tf32_kernel<<<WB, 256>>>(Wo, (float*)pWo);

    dim3 ggrid(DMODEL / 128, MTOT / 128, 3);  // (8, 64, 3)
    gemm_qkv<<<ggrid, 256>>>((const float*)pX, (const float*)pWq,
                             (const float*)pWk, (const float*)pWv,
                             (float*)pQ, (float*)pK, (float*)pV);

    dim3 agrid(SEQ / 128, BSZ * NHEADS);      // (16, 64)
    attn_tf32<<<agrid, 256, attn_smem>>>((const float*)pQ, (const float*)pK,
                                         (const float*)pV, (float*)pO);

    dim3 ogrid(DMODEL / 128, MTOT / 128, 1);
    gemm_out<<<ogrid, 256>>>((const float*)pO, (const float*)pWo, bo, out);
}